// round 12
// baseline (speedup 1.0000x reference)
#include <cuda_runtime.h>
#include <cuda_bf16.h>
#include <cstdint>
#include <math.h>

#define N 8192
#define D 768
#define INV_T 20.0f
#define DIAG_SUB 2.0e13f      /* 1e12 * 20 */
#define EPSN 1e-8f

#define NT 64                  /* 8192/128 tile blocks per dim */
#define NTILES 2080            /* NT*(NT+1)/2 upper-tri tiles */
#define BK 32                  /* K bf16 per chunk */
#define NCH (D / BK)           /* 24 chunks per tile */
#define NSTG 4                 /* ring stages */
#define RED_BLOCKS (N / 256)   /* 32 */

#define BST 80                 /* smem row stride (64B data + 16 pad) */
#define TILE_BYTES (128 * BST) /* 10240 per operand per stage */
#define STG_BYTES (2 * TILE_BYTES)
#define RING_BYTES (NSTG * STG_BYTES)            /* 81920 */
#define SMEM_DYN (RING_BYTES + 2 * 4 * 128 * 4)  /* 86016 */

// ---------------------------------------------------------------------------
// device scratch (no cudaMalloc allowed)
// ---------------------------------------------------------------------------
__device__ __nv_bfloat16 g_xnb[N * D];
__device__ float g_s2[NT][N];          // per-(tile-slot, row) sums of exp(l-20)
__device__ float g_t[N];               // logits[i, i^1]
__device__ float g_partial[RED_BLOCKS];
__device__ unsigned int g_done = 0;    // last-block detector (self-resetting)

// ---------------------------------------------------------------------------
// PTX helpers (baseline PTX only)
// ---------------------------------------------------------------------------
__device__ __forceinline__ void cp_async16(uint32_t saddr, const void* gptr) {
    asm volatile("cp.async.cg.shared.global [%0], [%1], 16;"
                 :: "r"(saddr), "l"(__cvta_generic_to_global(gptr)) : "memory");
}
#define CP_COMMIT() asm volatile("cp.async.commit_group;" ::: "memory")
#define CP_WAIT(n)  asm volatile("cp.async.wait_group %0;" :: "n"(n) : "memory")

__device__ __forceinline__ void ldsm_x4(uint32_t* r, uint32_t addr) {
    asm volatile("ldmatrix.sync.aligned.m8n8.x4.shared.b16 {%0,%1,%2,%3}, [%4];"
                 : "=r"(r[0]), "=r"(r[1]), "=r"(r[2]), "=r"(r[3]) : "r"(addr));
}

__device__ __forceinline__ void mma_bf16(float* d, const uint32_t* a,
                                         uint32_t b0, uint32_t b1) {
    asm volatile(
        "mma.sync.aligned.m16n8k16.row.col.f32.bf16.bf16.f32 "
        "{%0,%1,%2,%3}, {%4,%5,%6,%7}, {%8,%9}, {%0,%1,%2,%3};"
        : "+f"(d[0]), "+f"(d[1]), "+f"(d[2]), "+f"(d[3])
        : "r"(a[0]), "r"(a[1]), "r"(a[2]), "r"(a[3]), "r"(b0), "r"(b1));
}

__device__ __forceinline__ void decode_tile(int t, int& ti, int& tj) {
    int i = (int)(64.5f - sqrtf(64.5f * 64.5f - 2.0f * (float)t));
    while (i * NT - i * (i - 1) / 2 > t) --i;
    while ((i + 1) * NT - (i + 1) * i / 2 <= t) ++i;
    ti = i;
    tj = i + (t - (i * NT - i * (i - 1) / 2));
}

// ---------------------------------------------------------------------------
// Kernel 1: warp-per-row normalize -> bf16. 6 float4/lane, warp-only reduce.
// grid = N/8, block = 256 (8 warps = 8 rows)
// ---------------------------------------------------------------------------
__global__ void normalize_kernel(const float* __restrict__ x) {
    const int lane = threadIdx.x & 31;
    const int row  = blockIdx.x * 8 + (threadIdx.x >> 5);

    const float4* xr = (const float4*)(x + (size_t)row * D);
    float4 v[6];
    float ss = 0.0f;
    #pragma unroll
    for (int it = 0; it < 6; ++it) {
        v[it] = xr[lane + it * 32];
        ss = fmaf(v[it].x, v[it].x, ss);
        ss = fmaf(v[it].y, v[it].y, ss);
        ss = fmaf(v[it].z, v[it].z, ss);
        ss = fmaf(v[it].w, v[it].w, ss);
    }
    #pragma unroll
    for (int o = 16; o; o >>= 1) ss += __shfl_xor_sync(0xffffffffu, ss, o);

    const float inv = 1.0f / fmaxf(sqrtf(ss), EPSN);
    uint2* yr = (uint2*)((char*)g_xnb + (size_t)row * (D * 2));
    #pragma unroll
    for (int it = 0; it < 6; ++it) {
        __nv_bfloat162 lo = __floats2bfloat162_rn(v[it].x * inv, v[it].y * inv);
        __nv_bfloat162 hi = __floats2bfloat162_rn(v[it].z * inv, v[it].w * inv);
        uint2 o2;
        o2.x = *(uint32_t*)&lo;
        o2.y = *(uint32_t*)&hi;
        yr[lane + it * 32] = o2;
    }
}

// ---------------------------------------------------------------------------
// Kernel 2: persistent upper-triangular bf16 sim-GEMM, fixed-max softmax.
// grid = #SMs, block = 512. 4-stage chunk ring rolling across tile bounds.
// (round-9 validated datapath)
// ---------------------------------------------------------------------------
__global__ void __launch_bounds__(512, 1) simloss_kernel() {
    extern __shared__ __align__(16) char smem[];

    const int tid  = threadIdx.x;
    const int lane = tid & 31;
    const int w    = tid >> 5;
    const int wm   = w & 3;
    const int wn   = w >> 2;
    const int G    = gridDim.x;

    const uint32_t sBase = (uint32_t)__cvta_generic_to_shared(smem);
    float* bufs  = (float*)(smem + RING_BYTES);          // [4][128] direct
    float* bufs2 = bufs + 4 * 128;                       // [4][128] transposed

    const int brow  = tid >> 2;
    const int bslot = tid & 3;

    int t_cur = blockIdx.x;
    if (t_cur >= NTILES) return;
    int ti, tj;
    decode_tile(t_cur, ti, tj);
    int r0 = ti * 128, j0 = tj * 128;

    int t_nxt = t_cur + G;
    bool has_nxt = (t_nxt < NTILES);
    int nti, ntj, nr0 = 0, nj0 = 0;
    if (has_nxt) { decode_tile(t_nxt, nti, ntj); nr0 = nti * 128; nj0 = ntj * 128; }

    // prologue: stages 0..2 = chunks 0..2 of first tile
    #pragma unroll
    for (int p = 0; p < NSTG - 1; ++p) {
        const uint32_t sStg = sBase + (uint32_t)p * STG_BYTES;
        cp_async16(sStg + brow * BST + bslot * 16,
                   (const char*)g_xnb + (size_t)(r0 + brow) * (D * 2) + p * 64 + bslot * 16);
        cp_async16(sStg + TILE_BYTES + brow * BST + bslot * 16,
                   (const char*)g_xnb + (size_t)(j0 + brow) * (D * 2) + p * 64 + bslot * 16);
        CP_COMMIT();
    }

    const uint32_t aRowOff = (wm * 32 + (lane & 15)) * BST + (lane >> 4) * 16;
    const uint32_t bRowOff = (wn * 32 + (lane & 15)) * BST + (lane >> 4) * 16;
    const int il_base   = wm * 32 + (lane >> 2);
    const int jcol_base = wn * 32 + (lane & 3) * 2;

    for (;;) {
        const bool diag = (r0 == j0);
        float acc[2][4][4];
        #pragma unroll
        for (int mt = 0; mt < 2; ++mt)
            #pragma unroll
            for (int nt = 0; nt < 4; ++nt)
                #pragma unroll
                for (int c = 0; c < 4; ++c) acc[mt][nt][c] = 0.0f;

        for (int kc = 0; kc < NCH; ++kc) {
            CP_WAIT(2);
            __syncthreads();

            // prefetch chunk kc+3 (rolls into next tile)
            {
                int p = kc + NSTG - 1;
                int pr0 = r0, pj0 = j0;
                bool go = true;
                if (p >= NCH) { p -= NCH; pr0 = nr0; pj0 = nj0; go = has_nxt; }
                if (go) {
                    const uint32_t sStg = sBase + (uint32_t)(p & 3) * STG_BYTES;
                    cp_async16(sStg + brow * BST + bslot * 16,
                               (const char*)g_xnb + (size_t)(pr0 + brow) * (D * 2) + p * 64 + bslot * 16);
                    cp_async16(sStg + TILE_BYTES + brow * BST + bslot * 16,
                               (const char*)g_xnb + (size_t)(pj0 + brow) * (D * 2) + p * 64 + bslot * 16);
                }
                CP_COMMIT();
            }

            const uint32_t sStg = sBase + (uint32_t)(kc & 3) * STG_BYTES;
            uint32_t af[2][2][4], bf[2][2][4];
            #pragma unroll
            for (int ks = 0; ks < 2; ++ks)
                #pragma unroll
                for (int mt = 0; mt < 2; ++mt)
                    ldsm_x4(af[ks][mt], sStg + aRowOff + mt * 16 * BST + ks * 32);
            #pragma unroll
            for (int ks = 0; ks < 2; ++ks)
                #pragma unroll
                for (int g = 0; g < 2; ++g)
                    ldsm_x4(bf[ks][g], sStg + TILE_BYTES + bRowOff + g * 16 * BST + ks * 32);

            #pragma unroll
            for (int ks = 0; ks < 2; ++ks)
                #pragma unroll
                for (int mt = 0; mt < 2; ++mt)
                    #pragma unroll
                    for (int nt = 0; nt < 4; ++nt) {
                        const int g = nt >> 1, hi = nt & 1;
                        mma_bf16(acc[mt][nt], af[ks][mt], bf[ks][g][hi], bf[ks][g][hi + 2]);
                    }
        }

        // ---- epilogue: exp(l - 20) in place, then plain-sum reductions ----
        if (!diag) {
            #pragma unroll
            for (int mt = 0; mt < 2; ++mt)
                #pragma unroll
                for (int nt = 0; nt < 4; ++nt)
                    #pragma unroll
                    for (int c = 0; c < 4; ++c)
                        acc[mt][nt][c] = __expf(fmaf(acc[mt][nt][c], INV_T, -INV_T));
        } else {
            #pragma unroll
            for (int mt = 0; mt < 2; ++mt)
                #pragma unroll
                for (int nt = 0; nt < 4; ++nt)
                    #pragma unroll
                    for (int c = 0; c < 4; ++c) {
                        const int i = r0 + il_base + mt * 16 + (c >> 1) * 8;
                        const int j = j0 + jcol_base + nt * 8 + (c & 1);
                        float l = acc[mt][nt][c] * INV_T;
                        if (j == i) l -= DIAG_SUB;
                        if (j == (i ^ 1)) g_t[i] = l;
                        acc[mt][nt][c] = __expf(l - INV_T);
                    }
        }

        // direct: per-row sums over 8 cols, merge lanes xor {1,2}
        #pragma unroll
        for (int mt = 0; mt < 2; ++mt)
            #pragma unroll
            for (int rh = 0; rh < 2; ++rh) {
                float s = 0.0f;
                #pragma unroll
                for (int nt = 0; nt < 4; ++nt)
                    #pragma unroll
                    for (int cp = 0; cp < 2; ++cp) s += acc[mt][nt][rh * 2 + cp];
                s += __shfl_xor_sync(0xffffffffu, s, 1);
                s += __shfl_xor_sync(0xffffffffu, s, 2);
                if ((lane & 3) == 0)
                    bufs[wn * 128 + il_base + mt * 16 + rh * 8] = s;
            }

        // transposed: per-col sums over 4 rows, merge lanes xor {4,8,16}
        if (!diag) {
            #pragma unroll
            for (int nt = 0; nt < 4; ++nt)
                #pragma unroll
                for (int cp = 0; cp < 2; ++cp) {
                    float s = acc[0][nt][cp] + acc[0][nt][2 + cp]
                            + acc[1][nt][cp] + acc[1][nt][2 + cp];
                    s += __shfl_xor_sync(0xffffffffu, s, 4);
                    s += __shfl_xor_sync(0xffffffffu, s, 8);
                    s += __shfl_xor_sync(0xffffffffu, s, 16);
                    if (lane < 4)
                        bufs2[wm * 128 + wn * 32 + nt * 8 + (lane & 3) * 2 + cp] = s;
                }
        }
        __syncthreads();

        if (tid < 128) {
            float S = bufs[tid] + bufs[128 + tid] + bufs[256 + tid] + bufs[384 + tid];
            g_s2[j0 >> 7][r0 + tid] = S;
            if (!diag) {
                float S2 = bufs2[tid] + bufs2[128 + tid] + bufs2[256 + tid] + bufs2[384 + tid];
                g_s2[r0 >> 7][j0 + tid] = S2;
            }
        }

        if (!has_nxt) break;
        r0 = nr0; j0 = nj0;
        t_nxt += G;
        has_nxt = (t_nxt < NTILES);
        if (has_nxt) { decode_tile(t_nxt, nti, ntj); nr0 = nti * 128; nj0 = ntj * 128; }
    }
}

// ---------------------------------------------------------------------------
// Kernel 3: per-row loss + two-level reduction; LAST block (threadfence
// reduction pattern) sums the 32 partials and writes the mean.
// ---------------------------------------------------------------------------
__global__ void reduce_rows_kernel(float* __restrict__ out) {
    const int row = blockIdx.x * 256 + threadIdx.x;
    __shared__ float red[8];
    __shared__ bool amLast;

    float S = 0.0f;
    #pragma unroll 8
    for (int s = 0; s < NT; ++s) S += g_s2[s][row];
    float li = (INV_T + logf(S)) - g_t[row];

    #pragma unroll
    for (int o = 16; o; o >>= 1) li += __shfl_down_sync(0xffffffffu, li, o);
    if ((threadIdx.x & 31) == 0) red[threadIdx.x >> 5] = li;
    __syncthreads();
    if (threadIdx.x < 8) {
        float v = red[threadIdx.x];
        #pragma unroll
        for (int o = 4; o; o >>= 1) v += __shfl_down_sync(0xffu, v, o);
        if (threadIdx.x == 0) g_partial[blockIdx.x] = v;
    }

    __threadfence();
    if (threadIdx.x == 0) {
        unsigned int prev = atomicAdd(&g_done, 1u);
        amLast = (prev == RED_BLOCKS - 1);
    }
    __syncthreads();
    if (amLast && threadIdx.x < 32) {
        float v = g_partial[threadIdx.x];
        #pragma unroll
        for (int o = 16; o; o >>= 1) v += __shfl_down_sync(0xffffffffu, v, o);
        if (threadIdx.x == 0) {
            out[0] = v * (1.0f / (float)N);
            g_done = 0;                 // reset for next graph replay
        }
    }
}

extern "C" void kernel_launch(void* const* d_in, const int* in_sizes, int n_in,
                              void* d_out, int out_size) {
    const float* x = (const float*)d_in[0];
    float* out = (float*)d_out;

    int nsm = 148;
    cudaDeviceGetAttribute(&nsm, cudaDevAttrMultiProcessorCount, 0);
    int grid = nsm < NTILES ? nsm : NTILES;

    cudaFuncSetAttribute(simloss_kernel,
                         cudaFuncAttributeMaxDynamicSharedMemorySize, SMEM_DYN);

    normalize_kernel<<<N / 8, 256>>>(x);
    simloss_kernel<<<grid, 512, SMEM_DYN>>>();
    reduce_rows_kernel<<<RED_BLOCKS, 256>>>(out);
}

// round 13
// speedup vs baseline: 1.5381x; 1.5381x over previous
#include <cuda_runtime.h>
#include <cuda_bf16.h>
#include <cstdint>
#include <math.h>

#define N 8192
#define D 768
#define INV_T 20.0f
#define DIAG_SUB 2.0e13f      /* 1e12 * 20 */
#define EPSN 1e-8f

#define NT 64                  /* 8192/128 tile blocks per dim */
#define NTILES 2080            /* NT*(NT+1)/2 upper-tri tiles */
#define BK 32                  /* K bf16 per chunk */
#define NCH (D / BK)           /* 24 chunks per tile */
#define NSTG 4                 /* ring stages */
#define RED_BLOCKS (N / 256)   /* 32 */

#define BST 80                 /* smem row stride (64B data + 16 pad) */
#define TILE_BYTES (128 * BST) /* 10240 per operand per stage */
#define STG_BYTES (2 * TILE_BYTES)
#define RING_BYTES (NSTG * STG_BYTES)            /* 81920 */
#define SMEM_DYN (RING_BYTES + 2 * 4 * 128 * 4)  /* 86016 */

// ---------------------------------------------------------------------------
// device scratch (no cudaMalloc allowed)
// ---------------------------------------------------------------------------
__device__ __nv_bfloat16 g_xnb[N * D];
__device__ float g_s2[NT][N];          // per-(tile-slot, row) sums of exp(l-20)
__device__ float g_t[N];               // logits[i, i^1]
__device__ float g_partial[RED_BLOCKS];

// ---------------------------------------------------------------------------
// PTX helpers (baseline PTX only)
// ---------------------------------------------------------------------------
__device__ __forceinline__ void cp_async16(uint32_t saddr, const void* gptr) {
    asm volatile("cp.async.cg.shared.global [%0], [%1], 16;"
                 :: "r"(saddr), "l"(__cvta_generic_to_global(gptr)) : "memory");
}
#define CP_COMMIT() asm volatile("cp.async.commit_group;" ::: "memory")
#define CP_WAIT(n)  asm volatile("cp.async.wait_group %0;" :: "n"(n) : "memory")

__device__ __forceinline__ void ldsm_x4(uint32_t* r, uint32_t addr) {
    asm volatile("ldmatrix.sync.aligned.m8n8.x4.shared.b16 {%0,%1,%2,%3}, [%4];"
                 : "=r"(r[0]), "=r"(r[1]), "=r"(r[2]), "=r"(r[3]) : "r"(addr));
}

__device__ __forceinline__ void mma_bf16(float* d, const uint32_t* a,
                                         uint32_t b0, uint32_t b1) {
    asm volatile(
        "mma.sync.aligned.m16n8k16.row.col.f32.bf16.bf16.f32 "
        "{%0,%1,%2,%3}, {%4,%5,%6,%7}, {%8,%9}, {%0,%1,%2,%3};"
        : "+f"(d[0]), "+f"(d[1]), "+f"(d[2]), "+f"(d[3])
        : "r"(a[0]), "r"(a[1]), "r"(a[2]), "r"(a[3]), "r"(b0), "r"(b1));
}

__device__ __forceinline__ void decode_tile(int t, int& ti, int& tj) {
    int i = (int)(64.5f - sqrtf(64.5f * 64.5f - 2.0f * (float)t));
    while (i * NT - i * (i - 1) / 2 > t) --i;
    while ((i + 1) * NT - (i + 1) * i / 2 <= t) ++i;
    ti = i;
    tj = i + (t - (i * NT - i * (i - 1) / 2));
}

// ---------------------------------------------------------------------------
// Kernel 1: warp-per-row normalize -> bf16. 6 float4/lane, warp-only reduce.
// grid = N/8, block = 256 (8 warps = 8 rows)
// ---------------------------------------------------------------------------
__global__ void normalize_kernel(const float* __restrict__ x) {
    const int lane = threadIdx.x & 31;
    const int row  = blockIdx.x * 8 + (threadIdx.x >> 5);

    const float4* xr = (const float4*)(x + (size_t)row * D);
    float4 v[6];
    float ss = 0.0f;
    #pragma unroll
    for (int it = 0; it < 6; ++it) {
        v[it] = xr[lane + it * 32];
        ss = fmaf(v[it].x, v[it].x, ss);
        ss = fmaf(v[it].y, v[it].y, ss);
        ss = fmaf(v[it].z, v[it].z, ss);
        ss = fmaf(v[it].w, v[it].w, ss);
    }
    #pragma unroll
    for (int o = 16; o; o >>= 1) ss += __shfl_xor_sync(0xffffffffu, ss, o);

    const float inv = 1.0f / fmaxf(sqrtf(ss), EPSN);
    uint2* yr = (uint2*)((char*)g_xnb + (size_t)row * (D * 2));
    #pragma unroll
    for (int it = 0; it < 6; ++it) {
        __nv_bfloat162 lo = __floats2bfloat162_rn(v[it].x * inv, v[it].y * inv);
        __nv_bfloat162 hi = __floats2bfloat162_rn(v[it].z * inv, v[it].w * inv);
        uint2 o2;
        o2.x = *(uint32_t*)&lo;
        o2.y = *(uint32_t*)&hi;
        yr[lane + it * 32] = o2;
    }
}

// ---------------------------------------------------------------------------
// Kernel 2: persistent upper-triangular bf16 sim-GEMM, fixed-max softmax.
// grid = #SMs, block = 512. 4-stage chunk ring rolling across tile bounds.
// (round-9 validated datapath, unchanged)
// ---------------------------------------------------------------------------
__global__ void __launch_bounds__(512, 1) simloss_kernel() {
    extern __shared__ __align__(16) char smem[];

    const int tid  = threadIdx.x;
    const int lane = tid & 31;
    const int w    = tid >> 5;
    const int wm   = w & 3;
    const int wn   = w >> 2;
    const int G    = gridDim.x;

    const uint32_t sBase = (uint32_t)__cvta_generic_to_shared(smem);
    float* bufs  = (float*)(smem + RING_BYTES);          // [4][128] direct
    float* bufs2 = bufs + 4 * 128;                       // [4][128] transposed

    const int brow  = tid >> 2;
    const int bslot = tid & 3;

    int t_cur = blockIdx.x;
    if (t_cur >= NTILES) return;
    int ti, tj;
    decode_tile(t_cur, ti, tj);
    int r0 = ti * 128, j0 = tj * 128;

    int t_nxt = t_cur + G;
    bool has_nxt = (t_nxt < NTILES);
    int nti, ntj, nr0 = 0, nj0 = 0;
    if (has_nxt) { decode_tile(t_nxt, nti, ntj); nr0 = nti * 128; nj0 = ntj * 128; }

    // prologue: stages 0..2 = chunks 0..2 of first tile
    #pragma unroll
    for (int p = 0; p < NSTG - 1; ++p) {
        const uint32_t sStg = sBase + (uint32_t)p * STG_BYTES;
        cp_async16(sStg + brow * BST + bslot * 16,
                   (const char*)g_xnb + (size_t)(r0 + brow) * (D * 2) + p * 64 + bslot * 16);
        cp_async16(sStg + TILE_BYTES + brow * BST + bslot * 16,
                   (const char*)g_xnb + (size_t)(j0 + brow) * (D * 2) + p * 64 + bslot * 16);
        CP_COMMIT();
    }

    const uint32_t aRowOff = (wm * 32 + (lane & 15)) * BST + (lane >> 4) * 16;
    const uint32_t bRowOff = (wn * 32 + (lane & 15)) * BST + (lane >> 4) * 16;
    const int il_base   = wm * 32 + (lane >> 2);
    const int jcol_base = wn * 32 + (lane & 3) * 2;

    for (;;) {
        const bool diag = (r0 == j0);
        float acc[2][4][4];
        #pragma unroll
        for (int mt = 0; mt < 2; ++mt)
            #pragma unroll
            for (int nt = 0; nt < 4; ++nt)
                #pragma unroll
                for (int c = 0; c < 4; ++c) acc[mt][nt][c] = 0.0f;

        for (int kc = 0; kc < NCH; ++kc) {
            CP_WAIT(2);
            __syncthreads();

            // prefetch chunk kc+3 (rolls into next tile)
            {
                int p = kc + NSTG - 1;
                int pr0 = r0, pj0 = j0;
                bool go = true;
                if (p >= NCH) { p -= NCH; pr0 = nr0; pj0 = nj0; go = has_nxt; }
                if (go) {
                    const uint32_t sStg = sBase + (uint32_t)(p & 3) * STG_BYTES;
                    cp_async16(sStg + brow * BST + bslot * 16,
                               (const char*)g_xnb + (size_t)(pr0 + brow) * (D * 2) + p * 64 + bslot * 16);
                    cp_async16(sStg + TILE_BYTES + brow * BST + bslot * 16,
                               (const char*)g_xnb + (size_t)(pj0 + brow) * (D * 2) + p * 64 + bslot * 16);
                }
                CP_COMMIT();
            }

            const uint32_t sStg = sBase + (uint32_t)(kc & 3) * STG_BYTES;
            uint32_t af[2][2][4], bf[2][2][4];
            #pragma unroll
            for (int ks = 0; ks < 2; ++ks)
                #pragma unroll
                for (int mt = 0; mt < 2; ++mt)
                    ldsm_x4(af[ks][mt], sStg + aRowOff + mt * 16 * BST + ks * 32);
            #pragma unroll
            for (int ks = 0; ks < 2; ++ks)
                #pragma unroll
                for (int g = 0; g < 2; ++g)
                    ldsm_x4(bf[ks][g], sStg + TILE_BYTES + bRowOff + g * 16 * BST + ks * 32);

            #pragma unroll
            for (int ks = 0; ks < 2; ++ks)
                #pragma unroll
                for (int mt = 0; mt < 2; ++mt)
                    #pragma unroll
                    for (int nt = 0; nt < 4; ++nt) {
                        const int g = nt >> 1, hi = nt & 1;
                        mma_bf16(acc[mt][nt], af[ks][mt], bf[ks][g][hi], bf[ks][g][hi + 2]);
                    }
        }

        // ---- epilogue: exp(l - 20) in place, then plain-sum reductions ----
        if (!diag) {
            #pragma unroll
            for (int mt = 0; mt < 2; ++mt)
                #pragma unroll
                for (int nt = 0; nt < 4; ++nt)
                    #pragma unroll
                    for (int c = 0; c < 4; ++c)
                        acc[mt][nt][c] = __expf(fmaf(acc[mt][nt][c], INV_T, -INV_T));
        } else {
            #pragma unroll
            for (int mt = 0; mt < 2; ++mt)
                #pragma unroll
                for (int nt = 0; nt < 4; ++nt)
                    #pragma unroll
                    for (int c = 0; c < 4; ++c) {
                        const int i = r0 + il_base + mt * 16 + (c >> 1) * 8;
                        const int j = j0 + jcol_base + nt * 8 + (c & 1);
                        float l = acc[mt][nt][c] * INV_T;
                        if (j == i) l -= DIAG_SUB;
                        if (j == (i ^ 1)) g_t[i] = l;
                        acc[mt][nt][c] = __expf(l - INV_T);
                    }
        }

        // direct: per-row sums over 8 cols, merge lanes xor {1,2}
        #pragma unroll
        for (int mt = 0; mt < 2; ++mt)
            #pragma unroll
            for (int rh = 0; rh < 2; ++rh) {
                float s = 0.0f;
                #pragma unroll
                for (int nt = 0; nt < 4; ++nt)
                    #pragma unroll
                    for (int cp = 0; cp < 2; ++cp) s += acc[mt][nt][rh * 2 + cp];
                s += __shfl_xor_sync(0xffffffffu, s, 1);
                s += __shfl_xor_sync(0xffffffffu, s, 2);
                if ((lane & 3) == 0)
                    bufs[wn * 128 + il_base + mt * 16 + rh * 8] = s;
            }

        // transposed: per-col sums over 4 rows, merge lanes xor {4,8,16}
        if (!diag) {
            #pragma unroll
            for (int nt = 0; nt < 4; ++nt)
                #pragma unroll
                for (int cp = 0; cp < 2; ++cp) {
                    float s = acc[0][nt][cp] + acc[0][nt][2 + cp]
                            + acc[1][nt][cp] + acc[1][nt][2 + cp];
                    s += __shfl_xor_sync(0xffffffffu, s, 4);
                    s += __shfl_xor_sync(0xffffffffu, s, 8);
                    s += __shfl_xor_sync(0xffffffffu, s, 16);
                    if (lane < 4)
                        bufs2[wm * 128 + wn * 32 + nt * 8 + (lane & 3) * 2 + cp] = s;
                }
        }
        __syncthreads();

        if (tid < 128) {
            float S = bufs[tid] + bufs[128 + tid] + bufs[256 + tid] + bufs[384 + tid];
            g_s2[j0 >> 7][r0 + tid] = S;
            if (!diag) {
                float S2 = bufs2[tid] + bufs2[128 + tid] + bufs2[256 + tid] + bufs2[384 + tid];
                g_s2[r0 >> 7][j0 + tid] = S2;
            }
        }

        if (!has_nxt) break;
        r0 = nr0; j0 = nj0;
        t_nxt += G;
        has_nxt = (t_nxt < NTILES);
        if (has_nxt) { decode_tile(t_nxt, nti, ntj); nr0 = nti * 128; nj0 = ntj * 128; }
    }
}

// ---------------------------------------------------------------------------
// Kernel 3: sum 64 slots per row -> per-row loss; block partial sums
// ---------------------------------------------------------------------------
__global__ void reduce_rows_kernel() {
    const int row = blockIdx.x * 256 + threadIdx.x;
    __shared__ float red[8];

    float S = 0.0f;
    #pragma unroll 8
    for (int s = 0; s < NT; ++s) S += g_s2[s][row];
    float li = (INV_T + logf(S)) - g_t[row];

    #pragma unroll
    for (int o = 16; o; o >>= 1) li += __shfl_down_sync(0xffffffffu, li, o);
    if ((threadIdx.x & 31) == 0) red[threadIdx.x >> 5] = li;
    __syncthreads();
    if (threadIdx.x < 8) {
        float v = red[threadIdx.x];
        #pragma unroll
        for (int o = 4; o; o >>= 1) v += __shfl_down_sync(0xffu, v, o);
        if (threadIdx.x == 0) g_partial[blockIdx.x] = v;
    }
}

// ---------------------------------------------------------------------------
// Kernel 4: final deterministic sum -> mean
// ---------------------------------------------------------------------------
__global__ void final_kernel(float* __restrict__ out) {
    float v = g_partial[threadIdx.x];
    #pragma unroll
    for (int o = 16; o; o >>= 1) v += __shfl_down_sync(0xffffffffu, v, o);
    if (threadIdx.x == 0) out[0] = v * (1.0f / (float)N);
}

extern "C" void kernel_launch(void* const* d_in, const int* in_sizes, int n_in,
                              void* d_out, int out_size) {
    const float* x = (const float*)d_in[0];
    float* out = (float*)d_out;

    int nsm = 148;
    cudaDeviceGetAttribute(&nsm, cudaDevAttrMultiProcessorCount, 0);
    int grid = nsm < NTILES ? nsm : NTILES;

    cudaFuncSetAttribute(simloss_kernel,
                         cudaFuncAttributeMaxDynamicSharedMemorySize, SMEM_DYN);

    normalize_kernel<<<N / 8, 256>>>(x);
    simloss_kernel<<<grid, 512, SMEM_DYN>>>();
    reduce_rows_kernel<<<RED_BLOCKS, 256>>>();
    final_kernel<<<1, 32>>>(out);
}